// round 1
// baseline (speedup 1.0000x reference)
#include <cuda_runtime.h>
#include <cuda_bf16.h>

// Scratch for e[b,n] (allocation-free rule: static __device__ array).
#define MAX_BN (128 * 10000)
__device__ float g_e[MAX_BN];

__global__ __launch_bounds__(1024, 1)
void mta_kernel(const float* __restrict__ x,
                const float* __restrict__ raw_x,
                const float* __restrict__ a,
                const float* __restrict__ adj,
                const int*  __restrict__ node_index,
                const int*  __restrict__ type_index,
                float* __restrict__ out,
                int B, int N, int din, int draw, int T)
{
    const int b   = blockIdx.x;
    const int tid = threadIdx.x;
    const int D   = din + draw;
    const int t   = type_index[b];
    const int ni  = node_index[0];

    extern __shared__ float sh[];
    float* sa = sh;                 // D floats: a[t, :]
    float* sm = sh + D;             // blockDim: online max
    float* ss = sm + blockDim.x;    // blockDim: online sum

    // Load the selected type's weight vector into shared memory.
    for (int i = tid; i < D; i += blockDim.x)
        sa[i] = a[(size_t)t * D + i];
    __syncthreads();

    // c1 = dot(x[b, node_index, :], a[t, :din]) — per-batch scalar, tiny.
    const float* xrow = x + ((size_t)b * N + ni) * din;
    float c1 = 0.f;
    for (int k = 0; k < din; k++)
        c1 = fmaf(xrow[k], sa[k], c1);

    // Phase 1: stream raw_x, compute e, online softmax stats per thread.
    const float4* r4  = (const float4*)(raw_x + (size_t)b * N * draw);
    float*        ge  = g_e + (size_t)b * N;
    const int     vec = draw >> 2;  // 16 for draw=64

    float m = -3.0e38f;
    float s = 0.f;
    for (int n = tid; n < N; n += blockDim.x) {
        const float4* rn = r4 + (size_t)n * vec;
        float dot = c1;
        #pragma unroll 16
        for (int i = 0; i < vec; i++) {
            float4 v = rn[i];
            dot = fmaf(v.x, sa[din + 4*i    ], dot);
            dot = fmaf(v.y, sa[din + 4*i + 1], dot);
            dot = fmaf(v.z, sa[din + 4*i + 2], dot);
            dot = fmaf(v.w, sa[din + 4*i + 3], dot);
        }
        float e = dot > 0.f ? dot : 0.01f * dot;   // leaky relu
        if (adj[n] > 0.f) {
            ge[n] = e;
            float nm = fmaxf(m, e);
            s = s * __expf(m - nm) + __expf(e - nm);
            m = nm;
        } else {
            ge[n] = -9.0e15f;                       // NEG_INF sentinel
        }
    }

    // Block reduction of (m, s) pairs.
    sm[tid] = m; ss[tid] = s;
    __syncthreads();
    for (int off = blockDim.x >> 1; off > 0; off >>= 1) {
        if (tid < off) {
            float m1 = sm[tid], s1 = ss[tid];
            float m2 = sm[tid + off], s2 = ss[tid + off];
            float nm = fmaxf(m1, m2);
            sm[tid] = nm;
            ss[tid] = s1 * __expf(m1 - nm) + s2 * __expf(m2 - nm);
        }
        __syncthreads();
    }
    const float M    = sm[0];
    const float invS = 1.f / ss[0];

    // Phase 2: normalize (e scratch is L2-resident) and write output.
    float* ob = out + (size_t)b * N;
    for (int n = tid; n < N; n += blockDim.x) {
        float av = adj[n];
        ob[n] = (av > 0.f) ? __expf(ge[n] - M) * invS * av : 0.f;
    }
}

extern "C" void kernel_launch(void* const* d_in, const int* in_sizes, int n_in,
                              void* d_out, int out_size)
{
    const float* x    = (const float*)d_in[0];
    const float* rawx = (const float*)d_in[1];
    const float* a    = (const float*)d_in[2];
    const float* adj  = (const float*)d_in[3];
    const int*   nidx = (const int*)d_in[4];
    const int*   tidx = (const int*)d_in[5];
    float*       out  = (float*)d_out;

    const int B    = in_sizes[5];                 // type_index: (B,)
    const int N    = in_sizes[3];                 // adj_mask:   (N,)
    const int din  = in_sizes[0] / (B * N);       // x:     (B,N,din)
    const int draw = in_sizes[1] / (B * N);       // raw_x: (B,N,draw)
    const int D    = din + draw;
    const int T    = in_sizes[2] / D;             // a: (T,D,1)

    const int threads = 1024;
    const size_t shmem = (size_t)(D + 2 * threads) * sizeof(float);
    mta_kernel<<<B, threads, shmem>>>(x, rawx, a, adj, nidx, tidx, out,
                                      B, N, din, draw, T);
}

// round 7
// speedup vs baseline: 1.0108x; 1.0108x over previous
#include <cuda_runtime.h>
#include <cuda_bf16.h>

// Scratch for e[b,n] (allocation-free rule: static __device__ array).
#define MAX_BN (128 * 10000)
__device__ float g_e[MAX_BN];

// ---------------------------------------------------------------------------
// Fast path: draw == 64. Warp processes 2 nodes per LDG.128 (16 lanes/node,
// each lane one float4) -> 512B contiguous per warp-load, fully coalesced.
// ---------------------------------------------------------------------------
__global__ __launch_bounds__(1024, 1)
void mta_kernel64(const float* __restrict__ x,
                  const float* __restrict__ raw_x,
                  const float* __restrict__ a,
                  const float* __restrict__ adj,
                  const int*  __restrict__ node_index,
                  const int*  __restrict__ type_index,
                  float* __restrict__ out,
                  int B, int N, int din)
{
    const int b    = blockIdx.x;
    const int tid  = threadIdx.x;
    const int lane = tid & 31;
    const int w    = tid >> 5;          // warp id, 0..31
    const int sub  = lane >> 4;         // which node of the pair (0/1)
    const int ch   = lane & 15;         // float4 chunk within node
    const int D    = din + 64;
    const int t    = type_index[b];
    const int ni   = node_index[0];

    extern __shared__ float sh[];
    float* sa = sh;                      // D floats: a[t,:]
    float* sm = sh + D;                  // 1024: max reduce
    float* ss = sm + blockDim.x;         // 1024: sum reduce

    for (int i = tid; i < D; i += blockDim.x)
        sa[i] = a[(size_t)t * D + i];
    __syncthreads();

    // c1 = dot(x[b, node_index, :din], a[t, :din]) — uniform across block.
    const float* xrow = x + ((size_t)b * N + ni) * din;
    float c1 = 0.f;
    for (int k = 0; k < din; k++)
        c1 = fmaf(xrow[k], sa[k], c1);

    // Per-lane weight chunk (fixed for the whole loop).
    const float wa0 = sa[din + ch * 4 + 0];
    const float wa1 = sa[din + ch * 4 + 1];
    const float wa2 = sa[din + ch * 4 + 2];
    const float wa3 = sa[din + ch * 4 + 3];

    const float4* base = (const float4*)(raw_x + (size_t)b * N * 64);
    float*        ge   = g_e + (size_t)b * N;

    const int numPairs = N >> 1;
    float m = -3.0e38f;
    float s = 0.f;

    // Unroll x4: 4 independent 512B warp-loads in flight (MLP>=4).
    for (int p = w; p < numPairs; p += 32 * 4) {
        float4 v[4];
        int    pj[4];
        #pragma unroll
        for (int j = 0; j < 4; j++) {
            pj[j] = p + j * 32;
            if (pj[j] < numPairs)
                v[j] = base[(size_t)pj[j] * 32 + lane];   // 32 float4s per pair
        }
        #pragma unroll
        for (int j = 0; j < 4; j++) {
            if (pj[j] >= numPairs) break;
            float dot = v[j].x * wa0;
            dot = fmaf(v[j].y, wa1, dot);
            dot = fmaf(v[j].z, wa2, dot);
            dot = fmaf(v[j].w, wa3, dot);
            // butterfly over the 16-lane half-warp group
            dot += __shfl_xor_sync(0xffffffffu, dot, 8);
            dot += __shfl_xor_sync(0xffffffffu, dot, 4);
            dot += __shfl_xor_sync(0xffffffffu, dot, 2);
            dot += __shfl_xor_sync(0xffffffffu, dot, 1);
            if (ch == 0) {
                const int n = pj[j] * 2 + sub;
                float e = c1 + dot;
                e = e > 0.f ? e : 0.01f * e;              // leaky relu
                if (adj[n] > 0.f) {
                    ge[n] = e;
                    float nm = fmaxf(m, e);
                    s = s * __expf(m - nm) + __expf(e - nm);
                    m = nm;
                } else {
                    ge[n] = -9.0e15f;
                }
            }
        }
    }

    // Odd tail node handled by thread 0.
    if ((N & 1) && tid == 0) {
        const int n = N - 1;
        const float* rn = raw_x + ((size_t)b * N + n) * 64;
        float e = c1;
        for (int k = 0; k < 64; k++) e = fmaf(rn[k], sa[din + k], e);
        e = e > 0.f ? e : 0.01f * e;
        if (adj[n] > 0.f) {
            ge[n] = e;
            float nm = fmaxf(m, e);
            s = s * __expf(m - nm) + __expf(e - nm);
            m = nm;
        } else ge[n] = -9.0e15f;
    }

    // Block reduction of (m, s).
    sm[tid] = m; ss[tid] = s;
    __syncthreads();
    for (int off = blockDim.x >> 1; off > 0; off >>= 1) {
        if (tid < off) {
            float m1 = sm[tid], s1 = ss[tid];
            float m2 = sm[tid + off], s2 = ss[tid + off];
            float nm = fmaxf(m1, m2);
            sm[tid] = nm;
            ss[tid] = s1 * __expf(m1 - nm) + s2 * __expf(m2 - nm);
        }
        __syncthreads();
    }
    const float M    = sm[0];
    const float invS = 1.f / ss[0];

    // Phase 2: normalize (e scratch is L2-resident) and write output.
    float* ob = out + (size_t)b * N;
    for (int n = tid; n < N; n += blockDim.x) {
        float av = adj[n];
        ob[n] = (av > 0.f) ? __expf(ge[n] - M) * invS * av : 0.f;
    }
}

// ---------------------------------------------------------------------------
// Generic fallback (previous kernel) for draw != 64.
// ---------------------------------------------------------------------------
__global__ __launch_bounds__(1024, 1)
void mta_kernel_gen(const float* __restrict__ x,
                    const float* __restrict__ raw_x,
                    const float* __restrict__ a,
                    const float* __restrict__ adj,
                    const int*  __restrict__ node_index,
                    const int*  __restrict__ type_index,
                    float* __restrict__ out,
                    int B, int N, int din, int draw)
{
    const int b   = blockIdx.x;
    const int tid = threadIdx.x;
    const int D   = din + draw;
    const int t   = type_index[b];
    const int ni  = node_index[0];

    extern __shared__ float sh[];
    float* sa = sh;
    float* sm = sh + D;
    float* ss = sm + blockDim.x;

    for (int i = tid; i < D; i += blockDim.x)
        sa[i] = a[(size_t)t * D + i];
    __syncthreads();

    const float* xrow = x + ((size_t)b * N + ni) * din;
    float c1 = 0.f;
    for (int k = 0; k < din; k++)
        c1 = fmaf(xrow[k], sa[k], c1);

    float* ge = g_e + (size_t)b * N;
    float m = -3.0e38f, s = 0.f;
    for (int n = tid; n < N; n += blockDim.x) {
        const float* rn = raw_x + ((size_t)b * N + n) * draw;
        float e = c1;
        for (int k = 0; k < draw; k++) e = fmaf(rn[k], sa[din + k], e);
        e = e > 0.f ? e : 0.01f * e;
        if (adj[n] > 0.f) {
            ge[n] = e;
            float nm = fmaxf(m, e);
            s = s * __expf(m - nm) + __expf(e - nm);
            m = nm;
        } else ge[n] = -9.0e15f;
    }

    sm[tid] = m; ss[tid] = s;
    __syncthreads();
    for (int off = blockDim.x >> 1; off > 0; off >>= 1) {
        if (tid < off) {
            float m1 = sm[tid], s1 = ss[tid];
            float m2 = sm[tid + off], s2 = ss[tid + off];
            float nm = fmaxf(m1, m2);
            sm[tid] = nm;
            ss[tid] = s1 * __expf(m1 - nm) + s2 * __expf(m2 - nm);
        }
        __syncthreads();
    }
    const float M = sm[0];
    const float invS = 1.f / ss[0];

    float* ob = out + (size_t)b * N;
    for (int n = tid; n < N; n += blockDim.x) {
        float av = adj[n];
        ob[n] = (av > 0.f) ? __expf(ge[n] - M) * invS * av : 0.f;
    }
}

extern "C" void kernel_launch(void* const* d_in, const int* in_sizes, int n_in,
                              void* d_out, int out_size)
{
    const float* x    = (const float*)d_in[0];
    const float* rawx = (const float*)d_in[1];
    const float* a    = (const float*)d_in[2];
    const float* adj  = (const float*)d_in[3];
    const int*   nidx = (const int*)d_in[4];
    const int*   tidx = (const int*)d_in[5];
    float*       out  = (float*)d_out;

    const int B    = in_sizes[5];
    const int N    = in_sizes[3];
    const int din  = in_sizes[0] / (B * N);
    const int draw = in_sizes[1] / (B * N);
    const int D    = din + draw;

    const int threads = 1024;
    const size_t shmem = (size_t)(D + 2 * threads) * sizeof(float);
    if (draw == 64) {
        mta_kernel64<<<B, threads, shmem>>>(x, rawx, a, adj, nidx, tidx, out,
                                            B, N, din);
    } else {
        mta_kernel_gen<<<B, threads, shmem>>>(x, rawx, a, adj, nidx, tidx, out,
                                              B, N, din, draw);
    }
}